// round 1
// baseline (speedup 1.0000x reference)
#include <cuda_runtime.h>
#include <math.h>
#include <stdint.h>

#define NLV   16
#define TBITS 19
#define TSZ   (1u << TBITS)
#define BLOCK 128

typedef unsigned long long u64;
typedef unsigned int u32;

struct LvlParams {
    float scale[NLV];
    int   res[NLV];
    int   dense[NLV];
};

// ---------------- packed f32x2 helpers ----------------
__device__ __forceinline__ u64 pack2(float lo, float hi) {
    u64 r;
    asm("mov.b64 %0, {%1, %2};" : "=l"(r)
        : "r"(__float_as_uint(lo)), "r"(__float_as_uint(hi)));
    return r;
}
__device__ __forceinline__ void unpack2(u64 v, float& lo, float& hi) {
    u32 a, b;
    asm("mov.b64 {%0, %1}, %2;" : "=r"(a), "=r"(b) : "l"(v));
    lo = __uint_as_float(a);
    hi = __uint_as_float(b);
}
__device__ __forceinline__ u64 ffma2(u64 a, u64 b, u64 c) {
    u64 d;
    asm("fma.rn.f32x2 %0, %1, %2, %3;" : "=l"(d) : "l"(a), "l"(b), "l"(c));
    return d;
}

// softplus(10 z) / 10, numerically stable; errors ~1e-7 abs (fine vs 1e-3 tol)
__device__ __forceinline__ float softplus10(float z) {
    float t = 10.0f * z;
    float e = __expf(-fabsf(t));
    return (fmaxf(t, 0.0f) + __logf(1.0f + e)) * 0.1f;
}

// ---------------- shared memory layout (bytes) ----------------
// w1 packed: [j=0..31][q=0..31] u64   -> 8192 B
// w2 packed: [j=0..63][q=0..31] u64   -> 16384 B
// w3 packed: [j=0..63][q=0..31] u64   -> 16384 B
// w4:        64 floats                -> 256 B
// h staging: 128 threads x 65 floats  -> 33280 B (stride 65 => conflict-free)
#define SM_W1 0
#define SM_W2 8192
#define SM_W3 24576
#define SM_W4 40960
#define SM_H  41216
#define SMEM_BYTES (41216 + 33280)

__global__ void __launch_bounds__(BLOCK, 3)
sdf_kernel(const float* __restrict__ x,
           const float* __restrict__ table,
           const float* __restrict__ w1,
           const float* __restrict__ w2,
           const float* __restrict__ w3,
           const float* __restrict__ w4,
           float* __restrict__ out,
           int n, LvlParams P)
{
    extern __shared__ char smem[];
    u64*   s_w1 = reinterpret_cast<u64*>(smem + SM_W1);
    u64*   s_w2 = reinterpret_cast<u64*>(smem + SM_W2);
    u64*   s_w3 = reinterpret_cast<u64*>(smem + SM_W3);
    float* s_w4 = reinterpret_cast<float*>(smem + SM_W4);
    float* s_h  = reinterpret_cast<float*>(smem + SM_H);

    // ---- pack weights into shared: s_w[j*32+q] = {W[2q][j], W[2q+1][j]} ----
    for (int t = threadIdx.x; t < 32 * 32; t += BLOCK) {
        int j = t >> 5, q = t & 31;
        s_w1[t] = pack2(w1[(2 * q) * 32 + j], w1[(2 * q + 1) * 32 + j]);
    }
    for (int t = threadIdx.x; t < 64 * 32; t += BLOCK) {
        int j = t >> 5, q = t & 31;
        s_w2[t] = pack2(w2[(2 * q) * 64 + j], w2[(2 * q + 1) * 64 + j]);
        s_w3[t] = pack2(w3[(2 * q) * 64 + j], w3[(2 * q + 1) * 64 + j]);
    }
    if (threadIdx.x < 64) s_w4[threadIdx.x] = w4[threadIdx.x];
    __syncthreads();

    int i = blockIdx.x * BLOCK + threadIdx.x;
    if (i >= n) return;

    float* sh = s_h + threadIdx.x * 65;  // per-thread activation row

    const float px = x[3 * i + 0];
    const float py = x[3 * i + 1];
    const float pz = x[3 * i + 2];

    // ------------------- hash-grid encoding -------------------
    #pragma unroll 1
    for (int l = 0; l < NLV; l++) {
        const float sc   = P.scale[l];
        const int   res  = P.res[l];
        const bool  dens = (P.dense[l] != 0);

        float fx = px * sc + 0.5f, fy = py * sc + 0.5f, fz = pz * sc + 0.5f;
        float gx = floorf(fx), gy = floorf(fy), gz = floorf(fz);
        float wx = fx - gx, wy = fy - gy, wz = fz - gz;
        int cx = (int)gx, cy = (int)gy, cz = (int)gz;

        const float2* tab = reinterpret_cast<const float2*>(table) + (size_t)l * TSZ;

        float f0 = 0.f, f1 = 0.f;
        #pragma unroll
        for (int c = 0; c < 8; c++) {
            const int ox = (c >> 2) & 1, oy = (c >> 1) & 1, oz = c & 1;
            u32 idx;
            if (dens) {
                int qx = min(max(cx + ox, 0), res - 1);
                int qy = min(max(cy + oy, 0), res - 1);
                int qz = min(max(cz + oz, 0), res - 1);
                idx = (u32)(qx + qy * res + qz * res * res);
            } else {
                u32 ux = (u32)(cx + ox), uy = (u32)(cy + oy), uz = (u32)(cz + oz);
                idx = (ux ^ (uy * 2654435761u) ^ (uz * 805459861u)) & (TSZ - 1u);
            }
            float2 f = __ldg(&tab[idx]);
            float wcx = ox ? wx : 1.f - wx;
            float wcy = oy ? wy : 1.f - wy;
            float wcz = oz ? wz : 1.f - wz;
            float wc = wcx * wcy * wcz;
            f0 = fmaf(wc, f.x, f0);
            f1 = fmaf(wc, f.y, f1);
        }
        sh[2 * l + 0] = f0;
        sh[2 * l + 1] = f1;
    }

    // ------------------- MLP (packed f32x2) -------------------
    u64 acc[32];

    // layer 1: 32 -> 64
    #pragma unroll
    for (int q = 0; q < 32; q++) acc[q] = 0ull;
    #pragma unroll 1
    for (int j = 0; j < 32; j++) {
        float v = sh[j];
        u64 e2 = pack2(v, v);
        const u64* wr = s_w1 + j * 32;
        #pragma unroll
        for (int q = 0; q < 32; q++) acc[q] = ffma2(e2, wr[q], acc[q]);
    }
    #pragma unroll
    for (int q = 0; q < 32; q++) {
        float a, b; unpack2(acc[q], a, b);
        sh[2 * q + 0] = softplus10(a);
        sh[2 * q + 1] = softplus10(b);
    }

    // layer 2: 64 -> 64
    #pragma unroll
    for (int q = 0; q < 32; q++) acc[q] = 0ull;
    #pragma unroll 1
    for (int j = 0; j < 64; j++) {
        float v = sh[j];
        u64 e2 = pack2(v, v);
        const u64* wr = s_w2 + j * 32;
        #pragma unroll
        for (int q = 0; q < 32; q++) acc[q] = ffma2(e2, wr[q], acc[q]);
    }
    #pragma unroll
    for (int q = 0; q < 32; q++) {
        float a, b; unpack2(acc[q], a, b);
        sh[2 * q + 0] = softplus10(a);
        sh[2 * q + 1] = softplus10(b);
    }

    // layer 3: 64 -> 64
    #pragma unroll
    for (int q = 0; q < 32; q++) acc[q] = 0ull;
    #pragma unroll 1
    for (int j = 0; j < 64; j++) {
        float v = sh[j];
        u64 e2 = pack2(v, v);
        const u64* wr = s_w3 + j * 32;
        #pragma unroll
        for (int q = 0; q < 32; q++) acc[q] = ffma2(e2, wr[q], acc[q]);
    }
    #pragma unroll
    for (int q = 0; q < 32; q++) {
        float a, b; unpack2(acc[q], a, b);
        sh[2 * q + 0] = softplus10(a);
        sh[2 * q + 1] = softplus10(b);
    }

    // layer 4: 64 -> 1
    float sdf = 0.f;
    #pragma unroll
    for (int j = 0; j < 64; j++) sdf = fmaf(sh[j], s_w4[j], sdf);

    out[i] = sdf;
}

extern "C" void kernel_launch(void* const* d_in, const int* in_sizes, int n_in,
                              void* d_out, int out_size)
{
    const float* x     = (const float*)d_in[0];
    const float* table = (const float*)d_in[1];
    const float* w1    = (const float*)d_in[2];
    const float* w2    = (const float*)d_in[3];
    const float* w3    = (const float*)d_in[4];
    const float* w4    = (const float*)d_in[5];
    float* out = (float*)d_out;

    const int n = in_sizes[0] / 3;

    // Level params in double, mirroring numpy's computation on the same libm.
    LvlParams P;
    const double pls = exp2(7.0 / 15.0);   // PER_LEVEL_SCALE, log2(2048/16)=7
    const double l2s = log2(pls);
    for (int l = 0; l < NLV; l++) {
        double s = exp2((double)l * l2s) * 16.0 - 1.0;
        P.scale[l] = (float)s;
        long long r = (long long)ceil(s) + 1;
        P.res[l] = (int)r;
        P.dense[l] = (r * r * r <= (long long)TSZ) ? 1 : 0;
    }

    cudaFuncSetAttribute(sdf_kernel,
                         cudaFuncAttributeMaxDynamicSharedMemorySize, SMEM_BYTES);

    int grid = (n + BLOCK - 1) / BLOCK;
    sdf_kernel<<<grid, BLOCK, SMEM_BYTES>>>(x, table, w1, w2, w3, w4, out, n, P);
}

// round 2
// speedup vs baseline: 1.0268x; 1.0268x over previous
#include <cuda_runtime.h>
#include <math.h>
#include <stdint.h>

#define NLV   16
#define TBITS 19
#define TSZ   (1u << TBITS)
#define BLOCK 128
#define IPT   2
#define HSTRIDE 129   // floats per thread staging: p0 at [0,63], p1 at [64,127]; 129 ≡ 1 mod 32 -> conflict-free

typedef unsigned long long u64;
typedef unsigned int u32;

struct LvlParams {
    float scale[NLV];
    int   res[NLV];
    int   dense[NLV];
};

// ---------------- packed f32x2 helpers ----------------
__device__ __forceinline__ u64 pack2(float lo, float hi) {
    u64 r;
    asm("mov.b64 %0, {%1, %2};" : "=l"(r)
        : "r"(__float_as_uint(lo)), "r"(__float_as_uint(hi)));
    return r;
}
__device__ __forceinline__ void unpack2(u64 v, float& lo, float& hi) {
    u32 a, b;
    asm("mov.b64 {%0, %1}, %2;" : "=r"(a), "=r"(b) : "l"(v));
    lo = __uint_as_float(a);
    hi = __uint_as_float(b);
}
__device__ __forceinline__ u64 ffma2(u64 a, u64 b, u64 c) {
    u64 d;
    asm("fma.rn.f32x2 %0, %1, %2, %3;" : "=l"(d) : "l"(a), "l"(b), "l"(c));
    return d;
}

// softplus(10 z) / 10, stable; abs err ~1e-7 (tolerance is 1e-3)
__device__ __forceinline__ float softplus10(float z) {
    float t = 10.0f * z;
    float e = __expf(-fabsf(t));
    return (fmaxf(t, 0.0f) + __logf(1.0f + e)) * 0.1f;
}

// ---------------- shared memory layout (bytes) ----------------
// w1 packed: [j=0..31][q=0..31] u64  -> 8192
// w2 packed: [j=0..63][q=0..31] u64  -> 16384
// w3 packed: [j=0..63][q=0..31] u64  -> 16384
// w4: 64 floats                      -> 256
// staging: 128 threads * 129 floats  -> 66048
#define SM_W1 0
#define SM_W2 8192
#define SM_W3 24576
#define SM_W4 40960
#define SM_H  41216
#define SMEM_BYTES (41216 + 66048)

// One MLP layer for 2 points: inputs sh[0..nin), sh[64..64+nin); outputs written back (64 each).
// Weights: sw[j*32+q] = {W[2q][j], W[2q+1][j]}, 16B-aligned.
__device__ __forceinline__ void mlp_layer(const u64* __restrict__ sw, float* __restrict__ sh, int nin) {
    u64 a0[32], a1[32];
    #pragma unroll
    for (int q = 0; q < 32; q++) { a0[q] = 0ull; a1[q] = 0ull; }

    #pragma unroll 1
    for (int j = 0; j < nin; j++) {
        float va = sh[j];
        float vb = sh[64 + j];
        u64 ea = pack2(va, va);
        u64 eb = pack2(vb, vb);
        const ulonglong2* wv = reinterpret_cast<const ulonglong2*>(sw + j * 32);
        #pragma unroll
        for (int q2 = 0; q2 < 16; q2++) {
            ulonglong2 ww = wv[q2];                 // LDS.128 broadcast
            a0[2*q2]   = ffma2(ea, ww.x, a0[2*q2]);
            a1[2*q2]   = ffma2(eb, ww.x, a1[2*q2]);
            a0[2*q2+1] = ffma2(ea, ww.y, a0[2*q2+1]);
            a1[2*q2+1] = ffma2(eb, ww.y, a1[2*q2+1]);
        }
    }

    #pragma unroll
    for (int q = 0; q < 32; q++) {
        float x0, x1, y0, y1;
        unpack2(a0[q], x0, x1);
        unpack2(a1[q], y0, y1);
        sh[2*q]        = softplus10(x0);
        sh[2*q + 1]    = softplus10(x1);
        sh[64 + 2*q]   = softplus10(y0);
        sh[64 + 2*q+1] = softplus10(y1);
    }
}

__global__ void __launch_bounds__(BLOCK, 2)
sdf_kernel(const float* __restrict__ x,
           const float* __restrict__ table,
           const float* __restrict__ w1,
           const float* __restrict__ w2,
           const float* __restrict__ w3,
           const float* __restrict__ w4,
           float* __restrict__ out,
           int n, LvlParams P)
{
    extern __shared__ char smem[];
    u64*   s_w1 = reinterpret_cast<u64*>(smem + SM_W1);
    u64*   s_w2 = reinterpret_cast<u64*>(smem + SM_W2);
    u64*   s_w3 = reinterpret_cast<u64*>(smem + SM_W3);
    float* s_w4 = reinterpret_cast<float*>(smem + SM_W4);
    float* s_h  = reinterpret_cast<float*>(smem + SM_H);

    // ---- pack weights into shared: s_w[j*32+q] = {W[2q][j], W[2q+1][j]} ----
    for (int t = threadIdx.x; t < 32 * 32; t += BLOCK) {
        int j = t >> 5, q = t & 31;
        s_w1[t] = pack2(w1[(2*q) * 32 + j], w1[(2*q + 1) * 32 + j]);
    }
    for (int t = threadIdx.x; t < 64 * 32; t += BLOCK) {
        int j = t >> 5, q = t & 31;
        s_w2[t] = pack2(w2[(2*q) * 64 + j], w2[(2*q + 1) * 64 + j]);
        s_w3[t] = pack2(w3[(2*q) * 64 + j], w3[(2*q + 1) * 64 + j]);
    }
    if (threadIdx.x < 64) s_w4[threadIdx.x] = w4[threadIdx.x];
    __syncthreads();

    const int i0 = blockIdx.x * (BLOCK * IPT) + threadIdx.x;
    const int i1 = i0 + BLOCK;
    if (i0 >= n) return;
    const bool has1 = (i1 < n);
    const int i1c = has1 ? i1 : i0;

    float* sh = s_h + threadIdx.x * HSTRIDE;

    const float px0 = x[3*i0+0], py0 = x[3*i0+1], pz0 = x[3*i0+2];
    const float px1 = x[3*i1c+0], py1 = x[3*i1c+1], pz1 = x[3*i1c+2];

    // ------------------- hash-grid encoding (2 points) -------------------
    #pragma unroll 1
    for (int l = 0; l < NLV; l++) {
        const float sc  = P.scale[l];
        const int   res = P.res[l];
        const bool  dens = (P.dense[l] != 0);
        const float2* tab = reinterpret_cast<const float2*>(table) + (size_t)l * TSZ;

        // point 0
        {
            float fx = px0*sc + 0.5f, fy = py0*sc + 0.5f, fz = pz0*sc + 0.5f;
            float gx = floorf(fx), gy = floorf(fy), gz = floorf(fz);
            float wx = fx-gx, wy = fy-gy, wz = fz-gz;
            int cx = (int)gx, cy = (int)gy, cz = (int)gz;
            float f0 = 0.f, f1 = 0.f;
            #pragma unroll
            for (int c = 0; c < 8; c++) {
                const int ox = (c>>2)&1, oy = (c>>1)&1, oz = c&1;
                u32 idx;
                if (dens) {
                    int qx = min(max(cx+ox,0),res-1);
                    int qy = min(max(cy+oy,0),res-1);
                    int qz = min(max(cz+oz,0),res-1);
                    idx = (u32)(qx + qy*res + qz*res*res);
                } else {
                    u32 ux=(u32)(cx+ox), uy=(u32)(cy+oy), uz=(u32)(cz+oz);
                    idx = (ux ^ (uy*2654435761u) ^ (uz*805459861u)) & (TSZ-1u);
                }
                float2 f = __ldg(&tab[idx]);
                float wc = (ox?wx:1.f-wx) * (oy?wy:1.f-wy) * (oz?wz:1.f-wz);
                f0 = fmaf(wc, f.x, f0);
                f1 = fmaf(wc, f.y, f1);
            }
            sh[2*l+0] = f0;
            sh[2*l+1] = f1;
        }
        // point 1
        {
            float fx = px1*sc + 0.5f, fy = py1*sc + 0.5f, fz = pz1*sc + 0.5f;
            float gx = floorf(fx), gy = floorf(fy), gz = floorf(fz);
            float wx = fx-gx, wy = fy-gy, wz = fz-gz;
            int cx = (int)gx, cy = (int)gy, cz = (int)gz;
            float f0 = 0.f, f1 = 0.f;
            #pragma unroll
            for (int c = 0; c < 8; c++) {
                const int ox = (c>>2)&1, oy = (c>>1)&1, oz = c&1;
                u32 idx;
                if (dens) {
                    int qx = min(max(cx+ox,0),res-1);
                    int qy = min(max(cy+oy,0),res-1);
                    int qz = min(max(cz+oz,0),res-1);
                    idx = (u32)(qx + qy*res + qz*res*res);
                } else {
                    u32 ux=(u32)(cx+ox), uy=(u32)(cy+oy), uz=(u32)(cz+oz);
                    idx = (ux ^ (uy*2654435761u) ^ (uz*805459861u)) & (TSZ-1u);
                }
                float2 f = __ldg(&tab[idx]);
                float wc = (ox?wx:1.f-wx) * (oy?wy:1.f-wy) * (oz?wz:1.f-wz);
                f0 = fmaf(wc, f.x, f0);
                f1 = fmaf(wc, f.y, f1);
            }
            sh[64 + 2*l+0] = f0;
            sh[64 + 2*l+1] = f1;
        }
    }

    // ------------------- MLP (packed f32x2, 2 points) -------------------
    mlp_layer(s_w1, sh, 32);   // 32 -> 64
    mlp_layer(s_w2, sh, 64);   // 64 -> 64
    mlp_layer(s_w3, sh, 64);   // 64 -> 64

    // layer 4: 64 -> 1 per point
    float sdf0 = 0.f, sdf1 = 0.f;
    #pragma unroll 8
    for (int j = 0; j < 64; j++) {
        float w = s_w4[j];
        sdf0 = fmaf(sh[j],      w, sdf0);
        sdf1 = fmaf(sh[64 + j], w, sdf1);
    }

    out[i0] = sdf0;
    if (has1) out[i1] = sdf1;
}

extern "C" void kernel_launch(void* const* d_in, const int* in_sizes, int n_in,
                              void* d_out, int out_size)
{
    const float* x     = (const float*)d_in[0];
    const float* table = (const float*)d_in[1];
    const float* w1    = (const float*)d_in[2];
    const float* w2    = (const float*)d_in[3];
    const float* w3    = (const float*)d_in[4];
    const float* w4    = (const float*)d_in[5];
    float* out = (float*)d_out;

    const int n = in_sizes[0] / 3;

    // Level params in double, mirroring numpy.
    LvlParams P;
    const double pls = exp2(7.0 / 15.0);   // PER_LEVEL_SCALE
    const double l2s = log2(pls);
    for (int l = 0; l < NLV; l++) {
        double s = exp2((double)l * l2s) * 16.0 - 1.0;
        P.scale[l] = (float)s;
        long long r = (long long)ceil(s) + 1;
        P.res[l] = (int)r;
        P.dense[l] = (r * r * r <= (long long)TSZ) ? 1 : 0;
    }

    cudaFuncSetAttribute(sdf_kernel,
                         cudaFuncAttributeMaxDynamicSharedMemorySize, SMEM_BYTES);

    const int per_block = BLOCK * IPT;
    int grid = (n + per_block - 1) / per_block;
    sdf_kernel<<<grid, BLOCK, SMEM_BYTES>>>(x, table, w1, w2, w3, w4, out, n, P);
}

// round 3
// speedup vs baseline: 3.0313x; 2.9523x over previous
#include <cuda_runtime.h>
#include <cuda_fp16.h>
#include <math.h>
#include <stdint.h>

#define NLV   16
#define TBITS 19
#define TSZ   (1u << TBITS)
#define BLOCK 256

typedef unsigned int u32;

struct LvlParams {
    float scale[NLV];
    int   res[NLV];
    int   dense[NLV];
};

// softplus(10 z)/10, stable fp32
__device__ __forceinline__ float softplus10(float z) {
    float t = 10.0f * z;
    float e = __expf(-fabsf(t));
    return (fmaxf(t, 0.0f) + __logf(1.0f + e)) * 0.1f;
}

// pack two f32 -> f16x2 (lo = first arg 'lo', hi = 'hi'); PTX cvt puts first src in HIGH half
__device__ __forceinline__ u32 f22h2(float hi, float lo) {
    u32 r;
    asm("cvt.rn.f16x2.f32 %0, %1, %2;" : "=r"(r) : "f"(hi), "f"(lo));
    return r;
}

__device__ __forceinline__ void ldsm4(u32& r0, u32& r1, u32& r2, u32& r3, u32 addr) {
    asm volatile("ldmatrix.sync.aligned.m8n8.x4.shared.b16 {%0,%1,%2,%3}, [%4];"
        : "=r"(r0), "=r"(r1), "=r"(r2), "=r"(r3) : "r"(addr));
}

__device__ __forceinline__ void mma16816(float* d, const u32* a, u32 b0, u32 b1) {
    asm volatile("mma.sync.aligned.m16n8k16.row.col.f32.f16.f16.f32 "
        "{%0,%1,%2,%3},{%4,%5,%6,%7},{%8,%9},{%0,%1,%2,%3};"
        : "+f"(d[0]), "+f"(d[1]), "+f"(d[2]), "+f"(d[3])
        : "r"(a[0]), "r"(a[1]), "r"(a[2]), "r"(a[3]), "r"(b0), "r"(b1));
}

__global__ void __launch_bounds__(BLOCK, 2)
sdf_kernel(const float* __restrict__ x,
           const float* __restrict__ table,
           const float* __restrict__ w1,
           const float* __restrict__ w2,
           const float* __restrict__ w3,
           const float* __restrict__ w4,
           float* __restrict__ out,
           int n, LvlParams P)
{
    // weights fp16 [out][in] with padded row strides (rows 16B-aligned, ldmatrix conflict-free)
    __shared__ __align__(16) __half s_w1[64 * 40];   //  5120 B, stride 40 halves (K=32)
    __shared__ __align__(16) __half s_w2[64 * 72];   //  9216 B, stride 72 halves (K=64)
    __shared__ __align__(16) __half s_w3[64 * 72];   //  9216 B
    __shared__ float s_w4[64];
    __shared__ __align__(16) __half s_enc[BLOCK * 40]; // 20480 B, row = block-local point, stride 40 halves

    const int tid  = threadIdx.x;
    const int lane = tid & 31;
    const int warp = tid >> 5;

    // ---- prologue: convert weights to fp16 smem ----
    for (int t = tid; t < 64 * 32; t += BLOCK) {
        int nn = t >> 5, kk = t & 31;
        s_w1[nn * 40 + kk] = __float2half_rn(w1[t]);
    }
    for (int t = tid; t < 64 * 64; t += BLOCK) {
        int nn = t >> 6, kk = t & 63;
        s_w2[nn * 72 + kk] = __float2half_rn(w2[t]);
        s_w3[nn * 72 + kk] = __float2half_rn(w3[t]);
    }
    if (tid < 64) s_w4[tid] = w4[tid];
    __syncthreads();

    // ---- encode (exact fp32, same math as the passing r1 kernel) ----
    const int i  = blockIdx.x * BLOCK + tid;
    const int ic = (i < n) ? i : (n - 1);
    const float px = x[3 * ic + 0];
    const float py = x[3 * ic + 1];
    const float pz = x[3 * ic + 2];

    u32* encw = reinterpret_cast<u32*>(s_enc);

    #pragma unroll 1
    for (int l = 0; l < NLV; l++) {
        const float sc  = P.scale[l];
        const int   res = P.res[l];
        const bool  dens = (P.dense[l] != 0);
        const float2* tab = reinterpret_cast<const float2*>(table) + (size_t)l * TSZ;

        float fx = px * sc + 0.5f, fy = py * sc + 0.5f, fz = pz * sc + 0.5f;
        float gx = floorf(fx), gy = floorf(fy), gz = floorf(fz);
        float wx = fx - gx, wy = fy - gy, wz = fz - gz;
        int cx = (int)gx, cy = (int)gy, cz = (int)gz;

        float f0 = 0.f, f1 = 0.f;
        #pragma unroll
        for (int c = 0; c < 8; c++) {
            const int ox = (c >> 2) & 1, oy = (c >> 1) & 1, oz = c & 1;
            u32 idx;
            if (dens) {
                int qx = min(max(cx + ox, 0), res - 1);
                int qy = min(max(cy + oy, 0), res - 1);
                int qz = min(max(cz + oz, 0), res - 1);
                idx = (u32)(qx + qy * res + qz * res * res);
            } else {
                u32 ux = (u32)(cx + ox), uy = (u32)(cy + oy), uz = (u32)(cz + oz);
                idx = (ux ^ (uy * 2654435761u) ^ (uz * 805459861u)) & (TSZ - 1u);
            }
            float2 f = __ldg(&tab[idx]);
            float wc = (ox ? wx : 1.f - wx) * (oy ? wy : 1.f - wy) * (oz ? wz : 1.f - wz);
            f0 = fmaf(wc, f.x, f0);
            f1 = fmaf(wc, f.y, f1);
        }
        // feats (2l, 2l+1) -> half2 {lo=f0, hi=f1} at enc[row=tid][halfpair=l]
        encw[tid * 20 + l] = f22h2(f1, f0);
    }
    __syncwarp();  // enc rows are warp-private (warp w owns rows [32w, 32w+32))

    // ---- MLP on tensor cores: warp handles its 32 points ----
    const u32 enc_b = (u32)__cvta_generic_to_shared(s_enc);
    const u32 w1_b  = (u32)__cvta_generic_to_shared(s_w1);
    const u32 w2_b  = (u32)__cvta_generic_to_shared(s_w2);
    const u32 w3_b  = (u32)__cvta_generic_to_shared(s_w3);

    float d[2][8][4];   // D: 2 m-tiles x 8 n-tiles x 4 f32
    u32   a[2][4][4];   // A: 2 m-tiles x up-to-4 k-tiles x 4 f16x2

    // --- layer 1: 32 -> 64 (A from enc smem) ---
    #pragma unroll
    for (int mt = 0; mt < 2; mt++)
        #pragma unroll
        for (int kt = 0; kt < 2; kt++) {
            u32 addr = enc_b + (u32)((warp * 32 + mt * 16 + (lane & 15)) * 80
                                     + kt * 32 + (lane >> 4) * 16);
            ldsm4(a[mt][kt][0], a[mt][kt][1], a[mt][kt][2], a[mt][kt][3], addr);
        }
    #pragma unroll
    for (int mt = 0; mt < 2; mt++)
        #pragma unroll
        for (int nt = 0; nt < 8; nt++)
            #pragma unroll
            for (int v = 0; v < 4; v++) d[mt][nt][v] = 0.f;

    #pragma unroll
    for (int kt = 0; kt < 2; kt++)
        #pragma unroll
        for (int u = 0; u < 4; u++) {
            u32 b0, b1, b2, b3;
            u32 addr = w1_b + (u32)((u * 16 + (lane >> 4) * 8 + (lane & 7)) * 80
                                    + kt * 32 + ((lane >> 3) & 1) * 16);
            ldsm4(b0, b1, b2, b3, addr);
            #pragma unroll
            for (int mt = 0; mt < 2; mt++) {
                mma16816(d[mt][2 * u],     a[mt][kt], b0, b1);
                mma16816(d[mt][2 * u + 1], a[mt][kt], b2, b3);
            }
        }

    // activation -> A fragments (register-only D->A identity)
    #pragma unroll
    for (int mt = 0; mt < 2; mt++)
        #pragma unroll
        for (int kk = 0; kk < 4; kk++) {
            a[mt][kk][0] = f22h2(softplus10(d[mt][2*kk][1]),   softplus10(d[mt][2*kk][0]));
            a[mt][kk][1] = f22h2(softplus10(d[mt][2*kk][3]),   softplus10(d[mt][2*kk][2]));
            a[mt][kk][2] = f22h2(softplus10(d[mt][2*kk+1][1]), softplus10(d[mt][2*kk+1][0]));
            a[mt][kk][3] = f22h2(softplus10(d[mt][2*kk+1][3]), softplus10(d[mt][2*kk+1][2]));
        }

    // --- layers 2 and 3: 64 -> 64 ---
    #pragma unroll 1
    for (int layer = 0; layer < 2; layer++) {
        const u32 wb = (layer == 0) ? w2_b : w3_b;
        #pragma unroll
        for (int mt = 0; mt < 2; mt++)
            #pragma unroll
            for (int nt = 0; nt < 8; nt++)
                #pragma unroll
                for (int v = 0; v < 4; v++) d[mt][nt][v] = 0.f;

        #pragma unroll
        for (int kt = 0; kt < 4; kt++)
            #pragma unroll
            for (int u = 0; u < 4; u++) {
                u32 b0, b1, b2, b3;
                u32 addr = wb + (u32)((u * 16 + (lane >> 4) * 8 + (lane & 7)) * 144
                                      + kt * 32 + ((lane >> 3) & 1) * 16);
                ldsm4(b0, b1, b2, b3, addr);
                #pragma unroll
                for (int mt = 0; mt < 2; mt++) {
                    mma16816(d[mt][2 * u],     a[mt][kt], b0, b1);
                    mma16816(d[mt][2 * u + 1], a[mt][kt], b2, b3);
                }
            }

        if (layer == 0) {
            #pragma unroll
            for (int mt = 0; mt < 2; mt++)
                #pragma unroll
                for (int kk = 0; kk < 4; kk++) {
                    a[mt][kk][0] = f22h2(softplus10(d[mt][2*kk][1]),   softplus10(d[mt][2*kk][0]));
                    a[mt][kk][1] = f22h2(softplus10(d[mt][2*kk][3]),   softplus10(d[mt][2*kk][2]));
                    a[mt][kk][2] = f22h2(softplus10(d[mt][2*kk+1][1]), softplus10(d[mt][2*kk+1][0]));
                    a[mt][kk][3] = f22h2(softplus10(d[mt][2*kk+1][3]), softplus10(d[mt][2*kk+1][2]));
                }
        }
    }

    // --- layer 4: 64 -> 1, fp32 scalar + quad reduce ---
    #pragma unroll
    for (int mt = 0; mt < 2; mt++) {
        float p0 = 0.f, p1 = 0.f;
        #pragma unroll
        for (int nt = 0; nt < 8; nt++) {
            int c = nt * 8 + 2 * (lane & 3);
            float wv0 = s_w4[c], wv1 = s_w4[c + 1];
            p0 = fmaf(softplus10(d[mt][nt][0]), wv0, p0);
            p0 = fmaf(softplus10(d[mt][nt][1]), wv1, p0);
            p1 = fmaf(softplus10(d[mt][nt][2]), wv0, p1);
            p1 = fmaf(softplus10(d[mt][nt][3]), wv1, p1);
        }
        p0 += __shfl_xor_sync(0xffffffffu, p0, 1);
        p0 += __shfl_xor_sync(0xffffffffu, p0, 2);
        p1 += __shfl_xor_sync(0xffffffffu, p1, 1);
        p1 += __shfl_xor_sync(0xffffffffu, p1, 2);
        if ((lane & 3) == 0) {
            int r0 = blockIdx.x * BLOCK + warp * 32 + mt * 16 + (lane >> 2);
            if (r0 < n) out[r0] = p0;
            int r1 = r0 + 8;
            if (r1 < n) out[r1] = p1;
        }
    }
}

extern "C" void kernel_launch(void* const* d_in, const int* in_sizes, int n_in,
                              void* d_out, int out_size)
{
    const float* x     = (const float*)d_in[0];
    const float* table = (const float*)d_in[1];
    const float* w1    = (const float*)d_in[2];
    const float* w2    = (const float*)d_in[3];
    const float* w3    = (const float*)d_in[4];
    const float* w4    = (const float*)d_in[5];
    float* out = (float*)d_out;

    const int n = in_sizes[0] / 3;

    LvlParams P;
    const double pls = exp2(7.0 / 15.0);
    const double l2s = log2(pls);
    for (int l = 0; l < NLV; l++) {
        double s = exp2((double)l * l2s) * 16.0 - 1.0;
        P.scale[l] = (float)s;
        long long r = (long long)ceil(s) + 1;
        P.res[l] = (int)r;
        P.dense[l] = (r * r * r <= (long long)TSZ) ? 1 : 0;
    }

    int grid = (n + BLOCK - 1) / BLOCK;
    sdf_kernel<<<grid, BLOCK>>>(x, table, w1, w2, w3, w4, out, n, P);
}